// round 2
// baseline (speedup 1.0000x reference)
#include <cuda_runtime.h>
#include <math.h>

#define Bn 8
#define Ln 2048
#define Cn 7
#define Dn 512
#define Wn 24
#define NF 56
#define EPSf 1e-5f
#define TT 16

// ---------------- scratch (device globals; allocation-free kernel_launch) ----
__device__ float g_xcomb[Bn*Ln*NF];
__device__ float g_c[(size_t)Bn*Ln*Dn];
__device__ float g_sq[Bn*Ln];
__device__ float g_rowsum[Bn*Ln];
__device__ float g_pe[Ln*Dn];
__device__ float g_pef[Ln*Dn];
__device__ float g_pel[Ln*Dn];
__device__ float g_S[(size_t)Bn*Ln*Ln];
__device__ float g_tsum[(size_t)Bn*Ln*Dn];

// ---------------- block reduce (blockDim == 256) ------------------------------
__device__ __forceinline__ float blockReduce(float v, float* red) {
    #pragma unroll
    for (int o = 16; o; o >>= 1) v += __shfl_xor_sync(0xffffffffu, v, o);
    if ((threadIdx.x & 31) == 0) red[threadIdx.x >> 5] = v;
    __syncthreads();
    float s = red[0];
    #pragma unroll
    for (int i = 1; i < 8; i++) s += red[i];
    __syncthreads();
    return s;
}

// ---------------- 1) window stats + lags --------------------------------------
__global__ __launch_bounds__(256)
void features_kernel(const float* __restrict__ x) {
    int gid = blockIdx.x * blockDim.x + threadIdx.x;
    if (gid >= Bn*Ln*Cn) return;
    int ch = gid % Cn;
    int t  = (gid / Cn) % Ln;
    int b  = gid / (Cn*Ln);
    const float* xb = x + (size_t)b*Ln*Cn;
    float v[Wn];
    #pragma unroll
    for (int w = 0; w < Wn; w++) {
        int tt = t - (Wn-1) + w; tt = tt < 0 ? 0 : tt;
        v[w] = xb[tt*Cn + ch];
    }
    float s = 0.f, mx = v[0], mn = v[0];
    #pragma unroll
    for (int w = 0; w < Wn; w++) { s += v[w]; mx = fmaxf(mx, v[w]); mn = fminf(mn, v[w]); }
    float mean = s * (1.0f/Wn);
    float m2 = 0.f;
    #pragma unroll
    for (int w = 0; w < Wn; w++) { float d = v[w]-mean; m2 += d*d; }
    float sd = sqrtf(m2 * (1.0f/(Wn-1)));
    float xc = v[Wn-1];
    int t3 = t-3; t3 = t3 < 0 ? 0 : t3;
    int t5 = t-5; t5 = t5 < 0 ? 0 : t5;
    int t7 = t-7; t7 = t7 < 0 ? 0 : t7;
    float* o = g_xcomb + ((size_t)b*Ln + t)*NF;
    o[ch]      = xc;
    o[7  + ch] = mean;
    o[14 + ch] = mx;
    o[21 + ch] = mn;
    o[28 + ch] = sd;
    o[35 + ch] = xc - xb[t3*Cn + ch];
    o[42 + ch] = xc - xb[t5*Cn + ch];
    o[49 + ch] = xc - xb[t7*Cn + ch];
}

// ---------------- 2) circular conv1d(k=3) + bias + LN + sumsq -----------------
__global__ __launch_bounds__(256)
void conv_ln_kernel(const float* __restrict__ conv_w, const float* __restrict__ conv_b,
                    const float* __restrict__ gamma_c, const float* __restrict__ beta_c) {
    __shared__ float sx[TT+2][NF];
    __shared__ float semb[TT][Dn];
    int b  = blockIdx.y;
    int t0 = blockIdx.x * TT;
    int tid = threadIdx.x;
    for (int i = tid; i < (TT+2)*NF; i += 256) {
        int r = i / NF, f = i - r*NF;
        int tt = (t0 - 1 + r + Ln) & (Ln - 1);
        sx[r][f] = g_xcomb[((size_t)b*Ln + tt)*NF + f];
    }
    __syncthreads();
    int d0 = tid * 2;
    float acc0[TT], acc1[TT];
    float bb0 = conv_b[d0], bb1 = conv_b[d0+1];
    #pragma unroll
    for (int t = 0; t < TT; t++) { acc0[t] = bb0; acc1[t] = bb1; }
    const float* w0p = conv_w + (size_t)d0*NF*3;
    const float* w1p = w0p + NF*3;
    for (int f = 0; f < NF; f++) {
        float w00 = w0p[f*3+0], w01 = w0p[f*3+1], w02 = w0p[f*3+2];
        float w10 = w1p[f*3+0], w11 = w1p[f*3+1], w12 = w1p[f*3+2];
        float sv[TT+2];
        #pragma unroll
        for (int r = 0; r < TT+2; r++) sv[r] = sx[r][f];
        #pragma unroll
        for (int t = 0; t < TT; t++) {
            acc0[t] += sv[t]*w00 + sv[t+1]*w01 + sv[t+2]*w02;
            acc1[t] += sv[t]*w10 + sv[t+1]*w11 + sv[t+2]*w12;
        }
    }
    #pragma unroll
    for (int t = 0; t < TT; t++) { semb[t][d0] = acc0[t]; semb[t][d0+1] = acc1[t]; }
    __syncthreads();
    int warp = tid >> 5, lane = tid & 31;
    for (int rr = warp; rr < TT; rr += 8) {
        float s = 0.f;
        for (int i = lane; i < Dn; i += 32) s += semb[rr][i];
        #pragma unroll
        for (int o = 16; o; o >>= 1) s += __shfl_xor_sync(0xffffffffu, s, o);
        float mu = s * (1.0f/Dn);
        float q = 0.f;
        for (int i = lane; i < Dn; i += 32) { float d = semb[rr][i]-mu; q += d*d; }
        #pragma unroll
        for (int o = 16; o; o >>= 1) q += __shfl_xor_sync(0xffffffffu, q, o);
        float inv = rsqrtf(q*(1.0f/Dn) + EPSf);
        int t = t0 + rr;
        float* cp = g_c + ((size_t)b*Ln + t)*Dn;
        float sq = 0.f;
        for (int i = lane; i < Dn; i += 32) {
            float cv = (semb[rr][i]-mu)*inv*gamma_c[i] + beta_c[i];
            cp[i] = cv;
            sq += cv*cv;
        }
        #pragma unroll
        for (int o = 16; o; o >>= 1) sq += __shfl_xor_sync(0xffffffffu, sq, o);
        if (lane == 0) g_sq[b*Ln + t] = sq;
    }
}

// ---------------- 3) sinusoid PE + LN(pe) + LN(pe_learned) --------------------
__global__ __launch_bounds__(256)
void pe_kernel(const float* __restrict__ pe_learned,
               const float* __restrict__ gf, const float* __restrict__ bf,
               const float* __restrict__ gl, const float* __restrict__ bl) {
    __shared__ float red[8];
    int t = blockIdx.x;
    int tid = threadIdx.x;
    int dA = tid, dB = tid + 256;
    const float kdiv = -9.210340371976184f / (float)Dn;
    float divA = expf((float)(dA & ~1) * kdiv);
    float divB = expf((float)(dB & ~1) * kdiv);
    float sA, cA, sB, cB;
    sincosf((float)t * divA, &sA, &cA);
    sincosf((float)t * divB, &sB, &cB);
    float v0 = (dA & 1) ? cA : sA;
    float v1 = (dB & 1) ? cB : sB;
    g_pe[t*Dn + dA] = v0;
    g_pe[t*Dn + dB] = v1;
    // LN(pe)
    float mu = blockReduce(v0 + v1, red) * (1.0f/Dn);
    float c0 = v0 - mu, c1 = v1 - mu;
    float var = blockReduce(c0*c0 + c1*c1, red) * (1.0f/Dn);
    float inv = rsqrtf(var + EPSf);
    g_pef[t*Dn + dA] = c0*inv*gf[dA] + bf[dA];
    g_pef[t*Dn + dB] = c1*inv*gf[dB] + bf[dB];
    // LN(pe_learned)
    float u0 = pe_learned[t*Dn + dA], u1 = pe_learned[t*Dn + dB];
    float mu2 = blockReduce(u0 + u1, red) * (1.0f/Dn);
    float e0 = u0 - mu2, e1 = u1 - mu2;
    float var2 = blockReduce(e0*e0 + e1*e1, red) * (1.0f/Dn);
    float inv2 = rsqrtf(var2 + EPSf);
    g_pel[t*Dn + dA] = e0*inv2*gl[dA] + bl[dA];
    g_pel[t*Dn + dB] = e1*inv2*gl[dB] + bl[dB];
}

// ---------------- 4) symmetric Gram + exp epilogue ----------------------------
__global__ __launch_bounds__(256)
void gram_kernel() {
    __shared__ float As[2][16][128];
    __shared__ float Bs[2][16][128];
    int b = blockIdx.y;
    int r = blockIdx.x, ti = 0;
    while (r >= 16 - ti) { r -= 16 - ti; ti++; }
    int tj = ti + r;
    const float* Cb = g_c + (size_t)b*Ln*Dn;
    int i0 = ti*128, j0 = tj*128;
    int tid = threadIdx.x;
    int tx = tid & 15, ty = tid >> 4;
    int rowT = tid >> 2, kT = (tid & 3) * 4;

    float acc[8][8];
    #pragma unroll
    for (int i = 0; i < 8; i++)
        #pragma unroll
        for (int j = 0; j < 8; j++) acc[i][j] = 0.f;

    const float* Ag = Cb + (size_t)(i0 + rowT)*Dn + kT;
    const float* Bg = Cb + (size_t)(j0 + rowT)*Dn + kT;

    float4 pa0 = *(const float4*)(Ag);
    float4 pa1 = *(const float4*)(Ag + 64*Dn);
    float4 pb0 = *(const float4*)(Bg);
    float4 pb1 = *(const float4*)(Bg + 64*Dn);
    #pragma unroll
    for (int q = 0; q < 4; q++) {
        As[0][kT+q][rowT]    = ((float*)&pa0)[q];
        As[0][kT+q][rowT+64] = ((float*)&pa1)[q];
        Bs[0][kT+q][rowT]    = ((float*)&pb0)[q];
        Bs[0][kT+q][rowT+64] = ((float*)&pb1)[q];
    }
    __syncthreads();
    int cur = 0;
    for (int kt = 0; kt < 32; kt++) {
        if (kt < 31) {
            int ko = (kt+1)*16;
            pa0 = *(const float4*)(Ag + ko);
            pa1 = *(const float4*)(Ag + 64*Dn + ko);
            pb0 = *(const float4*)(Bg + ko);
            pb1 = *(const float4*)(Bg + 64*Dn + ko);
        }
        #pragma unroll
        for (int k = 0; k < 16; k++) {
            float4 a0 = *(float4*)&As[cur][k][ty*4];
            float4 a1 = *(float4*)&As[cur][k][ty*4+64];
            float4 b0 = *(float4*)&Bs[cur][k][tx*4];
            float4 b1 = *(float4*)&Bs[cur][k][tx*4+64];
            float av[8] = {a0.x,a0.y,a0.z,a0.w,a1.x,a1.y,a1.z,a1.w};
            float bv[8] = {b0.x,b0.y,b0.z,b0.w,b1.x,b1.y,b1.z,b1.w};
            #pragma unroll
            for (int ri = 0; ri < 8; ri++)
                #pragma unroll
                for (int ci = 0; ci < 8; ci++) acc[ri][ci] += av[ri]*bv[ci];
        }
        if (kt < 31) {
            int nxt = cur ^ 1;
            #pragma unroll
            for (int q = 0; q < 4; q++) {
                As[nxt][kT+q][rowT]    = ((float*)&pa0)[q];
                As[nxt][kT+q][rowT+64] = ((float*)&pa1)[q];
                Bs[nxt][kT+q][rowT]    = ((float*)&pb0)[q];
                Bs[nxt][kT+q][rowT+64] = ((float*)&pb1)[q];
            }
            __syncthreads();
            cur = nxt;
        }
    }
    float* Sb = g_S + (size_t)b*Ln*Ln;
    int irow[8], jcol[8]; float sqi[8], sqj[8];
    #pragma unroll
    for (int rr = 0; rr < 8; rr++) {
        irow[rr] = i0 + ((rr<4) ? ty*4+rr : 64+ty*4+rr-4);
        jcol[rr] = j0 + ((rr<4) ? tx*4+rr : 64+tx*4+rr-4);
        sqi[rr] = g_sq[b*Ln + irow[rr]];
        sqj[rr] = g_sq[b*Ln + jcol[rr]];
    }
    #pragma unroll
    for (int rr = 0; rr < 8; rr++) {
        float sv[8];
        #pragma unroll
        for (int cc = 0; cc < 8; cc++) {
            float d = sqi[rr] + sqj[cc] - 2.0f*acc[rr][cc];
            d = fmaxf(d, 0.0f);
            sv[cc] = __expf(-0.5f * d);
        }
        float4* p0 = (float4*)&Sb[(size_t)irow[rr]*Ln + j0 + tx*4];
        float4* p1 = (float4*)&Sb[(size_t)irow[rr]*Ln + j0 + 64 + tx*4];
        *p0 = make_float4(sv[0], sv[1], sv[2], sv[3]);
        *p1 = make_float4(sv[4], sv[5], sv[6], sv[7]);
        if (ti != tj) {
            #pragma unroll
            for (int cc = 0; cc < 8; cc++)
                Sb[(size_t)jcol[cc]*Ln + irow[rr]] = sv[cc];
        }
    }
}

// ---------------- 5) row sums of S --------------------------------------------
__global__ __launch_bounds__(256)
void rowsum_kernel() {
    int row = blockIdx.x * 8 + (threadIdx.x >> 5);
    int lane = threadIdx.x & 31;
    const float4* p = (const float4*)(g_S + (size_t)row * Ln);
    float s = 0.f;
    #pragma unroll 4
    for (int i = lane; i < Ln/4; i += 32) {
        float4 v = p[i];
        s += (v.x + v.y) + (v.z + v.w);
    }
    #pragma unroll
    for (int o = 16; o; o >>= 1) s += __shfl_xor_sync(0xffffffffu, s, o);
    if (lane == 0) g_rowsum[row] = s;
}

// ---------------- 6) sem = S@c / rowsum, tsum = c + pe + sem ------------------
__global__ __launch_bounds__(256)
void sem_kernel() {
    __shared__ float As[2][16][128];
    __shared__ float Bs[2][16][128];
    int b  = blockIdx.z;
    int i0 = blockIdx.x * 128;
    int d0 = blockIdx.y * 128;
    const float* Cb = g_c + (size_t)b*Ln*Dn;
    const float* Sb = g_S + (size_t)b*Ln*Ln;
    int tid = threadIdx.x;
    int tx = tid & 15, ty = tid >> 4;
    int rowT = tid >> 2, kT = (tid & 3) * 4;
    int kB = tid >> 5, dB = (tid & 31) * 4;

    float acc[8][8];
    #pragma unroll
    for (int i = 0; i < 8; i++)
        #pragma unroll
        for (int j = 0; j < 8; j++) acc[i][j] = 0.f;

    const float* Ag = Sb + (size_t)(i0 + rowT)*Ln + kT;
    const float* Bg = Cb + (size_t)kB*Dn + d0 + dB;

    float4 pa0 = *(const float4*)(Ag);
    float4 pa1 = *(const float4*)(Ag + (size_t)64*Ln);
    float4 pb0 = *(const float4*)(Bg);
    float4 pb1 = *(const float4*)(Bg + 8*Dn);
    #pragma unroll
    for (int q = 0; q < 4; q++) {
        As[0][kT+q][rowT]    = ((float*)&pa0)[q];
        As[0][kT+q][rowT+64] = ((float*)&pa1)[q];
    }
    *(float4*)&Bs[0][kB][dB]   = pb0;
    *(float4*)&Bs[0][kB+8][dB] = pb1;
    __syncthreads();
    int cur = 0;
    for (int kt = 0; kt < 128; kt++) {
        if (kt < 127) {
            int ko = (kt+1)*16;
            pa0 = *(const float4*)(Ag + ko);
            pa1 = *(const float4*)(Ag + (size_t)64*Ln + ko);
            pb0 = *(const float4*)(Bg + (size_t)ko*Dn);
            pb1 = *(const float4*)(Bg + (size_t)(ko+8)*Dn);
        }
        #pragma unroll
        for (int k = 0; k < 16; k++) {
            float4 a0 = *(float4*)&As[cur][k][ty*4];
            float4 a1 = *(float4*)&As[cur][k][ty*4+64];
            float4 b0 = *(float4*)&Bs[cur][k][tx*4];
            float4 b1 = *(float4*)&Bs[cur][k][tx*4+64];
            float av[8] = {a0.x,a0.y,a0.z,a0.w,a1.x,a1.y,a1.z,a1.w};
            float bv[8] = {b0.x,b0.y,b0.z,b0.w,b1.x,b1.y,b1.z,b1.w};
            #pragma unroll
            for (int ri = 0; ri < 8; ri++)
                #pragma unroll
                for (int ci = 0; ci < 8; ci++) acc[ri][ci] += av[ri]*bv[ci];
        }
        if (kt < 127) {
            int nxt = cur ^ 1;
            #pragma unroll
            for (int q = 0; q < 4; q++) {
                As[nxt][kT+q][rowT]    = ((float*)&pa0)[q];
                As[nxt][kT+q][rowT+64] = ((float*)&pa1)[q];
            }
            *(float4*)&Bs[nxt][kB][dB]   = pb0;
            *(float4*)&Bs[nxt][kB+8][dB] = pb1;
            __syncthreads();
            cur = nxt;
        }
    }
    float* Tb = g_tsum + (size_t)b*Ln*Dn;
    #pragma unroll
    for (int rr = 0; rr < 8; rr++) {
        int i = i0 + ((rr<4) ? ty*4+rr : 64+ty*4+rr-4);
        float rinv = 1.0f / g_rowsum[b*Ln + i];
        #pragma unroll
        for (int g = 0; g < 2; g++) {
            int j = d0 + g*64 + tx*4;
            float4 cv = *(const float4*)&Cb[(size_t)i*Dn + j];
            float4 pv = *(const float4*)&g_pe[i*Dn + j];
            float4 ov;
            ov.x = cv.x + pv.x + acc[rr][g*4+0]*rinv;
            ov.y = cv.y + pv.y + acc[rr][g*4+1]*rinv;
            ov.z = cv.z + pv.z + acc[rr][g*4+2]*rinv;
            ov.w = cv.w + pv.w + acc[rr][g*4+3]*rinv;
            *(float4*)&Tb[(size_t)i*Dn + j] = ov;
        }
    }
}

// ---------------- 7) LN(tsum) + weighted mix ----------------------------------
__global__ __launch_bounds__(256)
void final_kernel(const float* __restrict__ wp,
                  const float* __restrict__ gt, const float* __restrict__ bt,
                  float* __restrict__ out) {
    __shared__ float red[8];
    int row = blockIdx.x;            // b*Ln + t
    int t = row & (Ln - 1);
    int tid = threadIdx.x;
    int dA = tid, dB = tid + 256;
    const float* tp = g_tsum + (size_t)row*Dn;
    float v0 = tp[dA], v1 = tp[dB];
    float mu = blockReduce(v0 + v1, red) * (1.0f/Dn);
    float c0 = v0 - mu, c1 = v1 - mu;
    float var = blockReduce(c0*c0 + c1*c1, red) * (1.0f/Dn);
    float inv = rsqrtf(var + EPSf);
    // softmax of 4 weights
    float w0 = wp[0], w1 = wp[1], w2 = wp[2], w3 = wp[3];
    float mx = fmaxf(fmaxf(w0, w1), fmaxf(w2, w3));
    float e0 = expf(w0-mx), e1 = expf(w1-mx), e2 = expf(w2-mx), e3 = expf(w3-mx);
    float esum = 1.0f / (e0+e1+e2+e3);
    w0 = e0*esum; w1 = e1*esum; w2 = e2*esum; w3 = e3*esum;
    const float* cp = g_c + (size_t)row*Dn;
    float tpe0 = c0*inv*gt[dA] + bt[dA];
    float tpe1 = c1*inv*gt[dB] + bt[dB];
    out[(size_t)row*Dn + dA] = w0*cp[dA] + w1*g_pef[t*Dn+dA] + w2*g_pel[t*Dn+dA] + w3*tpe0;
    out[(size_t)row*Dn + dB] = w0*cp[dB] + w1*g_pef[t*Dn+dB] + w2*g_pel[t*Dn+dB] + w3*tpe1;
}

// ---------------- launch ------------------------------------------------------
extern "C" void kernel_launch(void* const* d_in, const int* in_sizes, int n_in,
                              void* d_out, int out_size) {
    const float* x          = (const float*)d_in[0];
    const float* conv_w     = (const float*)d_in[1];
    const float* conv_b     = (const float*)d_in[2];
    const float* pe_learned = (const float*)d_in[3];
    const float* wp         = (const float*)d_in[4];
    const float* gamma_c    = (const float*)d_in[5];
    const float* beta_c     = (const float*)d_in[6];
    const float* gamma_f    = (const float*)d_in[7];
    const float* beta_f     = (const float*)d_in[8];
    const float* gamma_l    = (const float*)d_in[9];
    const float* beta_l     = (const float*)d_in[10];
    const float* gamma_t    = (const float*)d_in[11];
    const float* beta_t     = (const float*)d_in[12];

    features_kernel<<<(Bn*Ln*Cn + 255)/256, 256>>>(x);
    conv_ln_kernel<<<dim3(Ln/TT, Bn), 256>>>(conv_w, conv_b, gamma_c, beta_c);
    pe_kernel<<<Ln, 256>>>(pe_learned, gamma_f, beta_f, gamma_l, beta_l);
    gram_kernel<<<dim3(136, Bn), 256>>>();
    rowsum_kernel<<<Bn*Ln/8, 256>>>();
    sem_kernel<<<dim3(16, 4, Bn), 256>>>();
    final_kernel<<<Bn*Ln, 256>>>(wp, gamma_t, beta_t, (float*)d_out);
}

// round 3
// speedup vs baseline: 1.3998x; 1.3998x over previous
#include <cuda_runtime.h>
#include <math.h>

#define Bn 8
#define Ln 2048
#define Cn 7
#define Dn 512
#define Wn 24
#define NF 56
#define EPSf 1e-5f
#define TT 16

// ---------------- scratch (device globals; allocation-free kernel_launch) ----
__device__ float g_xcomb[Bn*Ln*NF];
__device__ float g_c[(size_t)Bn*Ln*Dn];
__device__ float g_sq[Bn*Ln];
__device__ float g_rowsum[Bn*Ln];
__device__ float g_pe[Ln*Dn];
__device__ float g_pef[Ln*Dn];
__device__ float g_pel[Ln*Dn];
__device__ float g_S[(size_t)Bn*Ln*Ln];
__device__ float g_tsum[(size_t)Bn*Ln*Dn];

// ---------------- helpers -----------------------------------------------------
__device__ __forceinline__ float totf(float x) {
    unsigned u;
    asm("cvt.rna.tf32.f32 %0, %1;" : "=r"(u) : "f"(x));
    return __uint_as_float(u);
}

__device__ __forceinline__ void mma_tf32(float* d, const unsigned* a, const unsigned* b) {
    asm volatile(
        "mma.sync.aligned.m16n8k8.row.col.f32.tf32.tf32.f32 "
        "{%0,%1,%2,%3}, {%4,%5,%6,%7}, {%8,%9}, {%0,%1,%2,%3};"
        : "+f"(d[0]), "+f"(d[1]), "+f"(d[2]), "+f"(d[3])
        : "r"(a[0]), "r"(a[1]), "r"(a[2]), "r"(a[3]), "r"(b[0]), "r"(b[1]));
}

__device__ __forceinline__ float blockReduce(float v, float* red) {
    #pragma unroll
    for (int o = 16; o; o >>= 1) v += __shfl_xor_sync(0xffffffffu, v, o);
    if ((threadIdx.x & 31) == 0) red[threadIdx.x >> 5] = v;
    __syncthreads();
    float s = red[0];
    #pragma unroll
    for (int i = 1; i < 8; i++) s += red[i];
    __syncthreads();
    return s;
}

// ---------------- 1) window stats + lags --------------------------------------
__global__ __launch_bounds__(256)
void features_kernel(const float* __restrict__ x) {
    int gid = blockIdx.x * blockDim.x + threadIdx.x;
    if (gid >= Bn*Ln*Cn) return;
    int ch = gid % Cn;
    int t  = (gid / Cn) % Ln;
    int b  = gid / (Cn*Ln);
    const float* xb = x + (size_t)b*Ln*Cn;
    float v[Wn];
    #pragma unroll
    for (int w = 0; w < Wn; w++) {
        int tt = t - (Wn-1) + w; tt = tt < 0 ? 0 : tt;
        v[w] = xb[tt*Cn + ch];
    }
    float s = 0.f, mx = v[0], mn = v[0];
    #pragma unroll
    for (int w = 0; w < Wn; w++) { s += v[w]; mx = fmaxf(mx, v[w]); mn = fminf(mn, v[w]); }
    float mean = s * (1.0f/Wn);
    float m2 = 0.f;
    #pragma unroll
    for (int w = 0; w < Wn; w++) { float d = v[w]-mean; m2 += d*d; }
    float sd = sqrtf(m2 * (1.0f/(Wn-1)));
    float xc = v[Wn-1];
    int t3 = t-3; t3 = t3 < 0 ? 0 : t3;
    int t5 = t-5; t5 = t5 < 0 ? 0 : t5;
    int t7 = t-7; t7 = t7 < 0 ? 0 : t7;
    float* o = g_xcomb + ((size_t)b*Ln + t)*NF;
    o[ch]      = xc;
    o[7  + ch] = mean;
    o[14 + ch] = mx;
    o[21 + ch] = mn;
    o[28 + ch] = sd;
    o[35 + ch] = xc - xb[t3*Cn + ch];
    o[42 + ch] = xc - xb[t5*Cn + ch];
    o[49 + ch] = xc - xb[t7*Cn + ch];
}

// ---------------- 2) circular conv1d(k=3) + bias + LN + sumsq -----------------
__global__ __launch_bounds__(256)
void conv_ln_kernel(const float* __restrict__ conv_w, const float* __restrict__ conv_b,
                    const float* __restrict__ gamma_c, const float* __restrict__ beta_c) {
    __shared__ float sx[TT+2][NF];
    __shared__ float semb[TT][Dn];
    int b  = blockIdx.y;
    int t0 = blockIdx.x * TT;
    int tid = threadIdx.x;
    for (int i = tid; i < (TT+2)*NF; i += 256) {
        int r = i / NF, f = i - r*NF;
        int tt = (t0 - 1 + r + Ln) & (Ln - 1);
        sx[r][f] = g_xcomb[((size_t)b*Ln + tt)*NF + f];
    }
    __syncthreads();
    int d0 = tid * 2;
    float acc0[TT], acc1[TT];
    float bb0 = conv_b[d0], bb1 = conv_b[d0+1];
    #pragma unroll
    for (int t = 0; t < TT; t++) { acc0[t] = bb0; acc1[t] = bb1; }
    const float* w0p = conv_w + (size_t)d0*NF*3;
    const float* w1p = w0p + NF*3;
    for (int f = 0; f < NF; f++) {
        float w00 = w0p[f*3+0], w01 = w0p[f*3+1], w02 = w0p[f*3+2];
        float w10 = w1p[f*3+0], w11 = w1p[f*3+1], w12 = w1p[f*3+2];
        float sv[TT+2];
        #pragma unroll
        for (int r = 0; r < TT+2; r++) sv[r] = sx[r][f];
        #pragma unroll
        for (int t = 0; t < TT; t++) {
            acc0[t] += sv[t]*w00 + sv[t+1]*w01 + sv[t+2]*w02;
            acc1[t] += sv[t]*w10 + sv[t+1]*w11 + sv[t+2]*w12;
        }
    }
    #pragma unroll
    for (int t = 0; t < TT; t++) { semb[t][d0] = acc0[t]; semb[t][d0+1] = acc1[t]; }
    __syncthreads();
    int warp = tid >> 5, lane = tid & 31;
    for (int rr = warp; rr < TT; rr += 8) {
        float s = 0.f;
        for (int i = lane; i < Dn; i += 32) s += semb[rr][i];
        #pragma unroll
        for (int o = 16; o; o >>= 1) s += __shfl_xor_sync(0xffffffffu, s, o);
        float mu = s * (1.0f/Dn);
        float q = 0.f;
        for (int i = lane; i < Dn; i += 32) { float d = semb[rr][i]-mu; q += d*d; }
        #pragma unroll
        for (int o = 16; o; o >>= 1) q += __shfl_xor_sync(0xffffffffu, q, o);
        float inv = rsqrtf(q*(1.0f/Dn) + EPSf);
        int t = t0 + rr;
        float* cp = g_c + ((size_t)b*Ln + t)*Dn;
        float sq = 0.f;
        for (int i = lane; i < Dn; i += 32) {
            float cv = (semb[rr][i]-mu)*inv*gamma_c[i] + beta_c[i];
            cp[i] = cv;
            sq += cv*cv;
        }
        #pragma unroll
        for (int o = 16; o; o >>= 1) sq += __shfl_xor_sync(0xffffffffu, sq, o);
        if (lane == 0) g_sq[b*Ln + t] = sq;
    }
}

// ---------------- 3) sinusoid PE + LN(pe) + LN(pe_learned) --------------------
__global__ __launch_bounds__(256)
void pe_kernel(const float* __restrict__ pe_learned,
               const float* __restrict__ gf, const float* __restrict__ bf,
               const float* __restrict__ gl, const float* __restrict__ bl) {
    __shared__ float red[8];
    int t = blockIdx.x;
    int tid = threadIdx.x;
    int dA = tid, dB = tid + 256;
    const float kdiv = -9.210340371976184f / (float)Dn;
    float divA = expf((float)(dA & ~1) * kdiv);
    float divB = expf((float)(dB & ~1) * kdiv);
    float sA, cA, sB, cB;
    sincosf((float)t * divA, &sA, &cA);
    sincosf((float)t * divB, &sB, &cB);
    float v0 = (dA & 1) ? cA : sA;
    float v1 = (dB & 1) ? cB : sB;
    g_pe[t*Dn + dA] = v0;
    g_pe[t*Dn + dB] = v1;
    float mu = blockReduce(v0 + v1, red) * (1.0f/Dn);
    float c0 = v0 - mu, c1 = v1 - mu;
    float var = blockReduce(c0*c0 + c1*c1, red) * (1.0f/Dn);
    float inv = rsqrtf(var + EPSf);
    g_pef[t*Dn + dA] = c0*inv*gf[dA] + bf[dA];
    g_pef[t*Dn + dB] = c1*inv*gf[dB] + bf[dB];
    float u0 = pe_learned[t*Dn + dA], u1 = pe_learned[t*Dn + dB];
    float mu2 = blockReduce(u0 + u1, red) * (1.0f/Dn);
    float e0 = u0 - mu2, e1 = u1 - mu2;
    float var2 = blockReduce(e0*e0 + e1*e1, red) * (1.0f/Dn);
    float inv2 = rsqrtf(var2 + EPSf);
    g_pel[t*Dn + dA] = e0*inv2*gl[dA] + bl[dA];
    g_pel[t*Dn + dB] = e1*inv2*gl[dB] + bl[dB];
}

// ---------------- 4) symmetric Gram (tf32 mma) + exp epilogue -----------------
__global__ __launch_bounds__(256)
void gram_kernel() {
    __shared__ float As[2][128][20];
    __shared__ float Bs[2][128][20];
    int b = blockIdx.y;
    int r = blockIdx.x, ti = 0;
    while (r >= 16 - ti) { r -= 16 - ti; ti++; }
    int tj = ti + r;
    const float* Cb = g_c + (size_t)b*Ln*Dn;
    int i0 = ti*128, j0 = tj*128;
    int tid = threadIdx.x;
    int warp = tid >> 5, lane = tid & 31;
    int wm = (warp >> 2) * 64;
    int wn = (warp & 3) * 32;
    int g = lane >> 2, th = lane & 3;

    int lrow = tid >> 1, lk = (tid & 1) * 8;
    const float* Ag = Cb + (size_t)(i0 + lrow)*Dn + lk;
    const float* Bg = Cb + (size_t)(j0 + lrow)*Dn + lk;

    float acc[4][4][4];
    #pragma unroll
    for (int fm = 0; fm < 4; fm++)
        #pragma unroll
        for (int fn = 0; fn < 4; fn++)
            #pragma unroll
            for (int q = 0; q < 4; q++) acc[fm][fn][q] = 0.f;

    float4 pa0 = *(const float4*)(Ag);
    float4 pa1 = *(const float4*)(Ag + 4);
    float4 pb0 = *(const float4*)(Bg);
    float4 pb1 = *(const float4*)(Bg + 4);
    #pragma unroll
    for (int q = 0; q < 4; q++) {
        As[0][lrow][lk+q]   = totf(((float*)&pa0)[q]);
        As[0][lrow][lk+4+q] = totf(((float*)&pa1)[q]);
        Bs[0][lrow][lk+q]   = totf(((float*)&pb0)[q]);
        Bs[0][lrow][lk+4+q] = totf(((float*)&pb1)[q]);
    }
    __syncthreads();
    int cur = 0;
    for (int kt = 0; kt < 32; kt++) {
        if (kt < 31) {
            int ko = (kt+1)*16;
            pa0 = *(const float4*)(Ag + ko);
            pa1 = *(const float4*)(Ag + ko + 4);
            pb0 = *(const float4*)(Bg + ko);
            pb1 = *(const float4*)(Bg + ko + 4);
        }
        #pragma unroll
        for (int k8 = 0; k8 < 16; k8 += 8) {
            unsigned af[4][4], bf_[4][2];
            #pragma unroll
            for (int fm = 0; fm < 4; fm++) {
                const float* ap = &As[cur][wm + fm*16 + g][k8 + th];
                af[fm][0] = __float_as_uint(ap[0]);
                af[fm][1] = __float_as_uint(ap[8*20]);
                af[fm][2] = __float_as_uint(ap[4]);
                af[fm][3] = __float_as_uint(ap[8*20 + 4]);
            }
            #pragma unroll
            for (int fn = 0; fn < 4; fn++) {
                const float* bp = &Bs[cur][wn + fn*8 + g][k8 + th];
                bf_[fn][0] = __float_as_uint(bp[0]);
                bf_[fn][1] = __float_as_uint(bp[4]);
            }
            #pragma unroll
            for (int fm = 0; fm < 4; fm++)
                #pragma unroll
                for (int fn = 0; fn < 4; fn++)
                    mma_tf32(acc[fm][fn], af[fm], bf_[fn]);
        }
        if (kt < 31) {
            int nxt = cur ^ 1;
            #pragma unroll
            for (int q = 0; q < 4; q++) {
                As[nxt][lrow][lk+q]   = totf(((float*)&pa0)[q]);
                As[nxt][lrow][lk+4+q] = totf(((float*)&pa1)[q]);
                Bs[nxt][lrow][lk+q]   = totf(((float*)&pb0)[q]);
                Bs[nxt][lrow][lk+4+q] = totf(((float*)&pb1)[q]);
            }
            __syncthreads();
            cur = nxt;
        }
    }
    float* Sb = g_S + (size_t)b*Ln*Ln;
    float sqj[4][2];
    #pragma unroll
    for (int fn = 0; fn < 4; fn++) {
        int j = j0 + wn + fn*8 + th*2;
        sqj[fn][0] = g_sq[b*Ln + j];
        sqj[fn][1] = g_sq[b*Ln + j + 1];
    }
    #pragma unroll
    for (int fm = 0; fm < 4; fm++) {
        #pragma unroll
        for (int rr = 0; rr < 2; rr++) {
            int i = i0 + wm + fm*16 + g + rr*8;
            float sqi = g_sq[b*Ln + i];
            #pragma unroll
            for (int fn = 0; fn < 4; fn++) {
                int j = j0 + wn + fn*8 + th*2;
                float d0v = fmaxf(sqi + sqj[fn][0] - 2.0f*acc[fm][fn][rr*2+0], 0.0f);
                float d1v = fmaxf(sqi + sqj[fn][1] - 2.0f*acc[fm][fn][rr*2+1], 0.0f);
                float s0 = __expf(-0.5f * d0v);
                float s1 = __expf(-0.5f * d1v);
                *(float2*)&Sb[(size_t)i*Ln + j] = make_float2(s0, s1);
                if (ti != tj) {
                    Sb[(size_t)j*Ln + i]     = s0;
                    Sb[(size_t)(j+1)*Ln + i] = s1;
                }
            }
        }
    }
}

// ---------------- 5) row sums of S --------------------------------------------
__global__ __launch_bounds__(256)
void rowsum_kernel() {
    int row = blockIdx.x * 8 + (threadIdx.x >> 5);
    int lane = threadIdx.x & 31;
    const float4* p = (const float4*)(g_S + (size_t)row * Ln);
    float s = 0.f;
    #pragma unroll 4
    for (int i = lane; i < Ln/4; i += 32) {
        float4 v = p[i];
        s += (v.x + v.y) + (v.z + v.w);
    }
    #pragma unroll
    for (int o = 16; o; o >>= 1) s += __shfl_xor_sync(0xffffffffu, s, o);
    if (lane == 0) g_rowsum[row] = s;
}

// ---------------- 6) sem = S@c / rowsum (tf32 mma), tsum = c + pe + sem -------
__global__ __launch_bounds__(256)
void sem_kernel() {
    __shared__ float As[2][128][20];
    __shared__ float Bs[2][16][136];
    int b  = blockIdx.z;
    int i0 = blockIdx.x * 128;
    int d0 = blockIdx.y * 128;
    const float* Cb = g_c + (size_t)b*Ln*Dn;
    const float* Sb = g_S + (size_t)b*Ln*Ln;
    int tid = threadIdx.x;
    int warp = tid >> 5, lane = tid & 31;
    int wm = (warp >> 2) * 64;
    int wn = (warp & 3) * 32;
    int g = lane >> 2, th = lane & 3;

    int lrow = tid >> 1, lk = (tid & 1) * 8;
    int kB = tid >> 4, dB = (tid & 15) * 8;
    const float* Ag = Sb + (size_t)(i0 + lrow)*Ln + lk;
    const float* Bg = Cb + (size_t)kB*Dn + d0 + dB;

    float acc[4][4][4];
    #pragma unroll
    for (int fm = 0; fm < 4; fm++)
        #pragma unroll
        for (int fn = 0; fn < 4; fn++)
            #pragma unroll
            for (int q = 0; q < 4; q++) acc[fm][fn][q] = 0.f;

    float4 pa0 = *(const float4*)(Ag);
    float4 pa1 = *(const float4*)(Ag + 4);
    float4 pb0 = *(const float4*)(Bg);
    float4 pb1 = *(const float4*)(Bg + 4);
    #pragma unroll
    for (int q = 0; q < 4; q++) {
        As[0][lrow][lk+q]   = totf(((float*)&pa0)[q]);
        As[0][lrow][lk+4+q] = totf(((float*)&pa1)[q]);
        Bs[0][kB][dB+q]     = totf(((float*)&pb0)[q]);
        Bs[0][kB][dB+4+q]   = totf(((float*)&pb1)[q]);
    }
    __syncthreads();
    int cur = 0;
    for (int kt = 0; kt < 128; kt++) {
        if (kt < 127) {
            int ko = (kt+1)*16;
            pa0 = *(const float4*)(Ag + ko);
            pa1 = *(const float4*)(Ag + ko + 4);
            pb0 = *(const float4*)(Bg + (size_t)ko*Dn);
            pb1 = *(const float4*)(Bg + (size_t)ko*Dn + 4);
        }
        #pragma unroll
        for (int k8 = 0; k8 < 16; k8 += 8) {
            unsigned af[4][4], bf_[4][2];
            #pragma unroll
            for (int fm = 0; fm < 4; fm++) {
                const float* ap = &As[cur][wm + fm*16 + g][k8 + th];
                af[fm][0] = __float_as_uint(ap[0]);
                af[fm][1] = __float_as_uint(ap[8*20]);
                af[fm][2] = __float_as_uint(ap[4]);
                af[fm][3] = __float_as_uint(ap[8*20 + 4]);
            }
            #pragma unroll
            for (int fn = 0; fn < 4; fn++) {
                const float* bp = &Bs[cur][k8 + th][wn + fn*8 + g];
                bf_[fn][0] = __float_as_uint(bp[0]);
                bf_[fn][1] = __float_as_uint(bp[4*136]);
            }
            #pragma unroll
            for (int fm = 0; fm < 4; fm++)
                #pragma unroll
                for (int fn = 0; fn < 4; fn++)
                    mma_tf32(acc[fm][fn], af[fm], bf_[fn]);
        }
        if (kt < 127) {
            int nxt = cur ^ 1;
            #pragma unroll
            for (int q = 0; q < 4; q++) {
                As[nxt][lrow][lk+q]   = totf(((float*)&pa0)[q]);
                As[nxt][lrow][lk+4+q] = totf(((float*)&pa1)[q]);
                Bs[nxt][kB][dB+q]     = totf(((float*)&pb0)[q]);
                Bs[nxt][kB][dB+4+q]   = totf(((float*)&pb1)[q]);
            }
            __syncthreads();
            cur = nxt;
        }
    }
    float* Tb = g_tsum + (size_t)b*Ln*Dn;
    #pragma unroll
    for (int fm = 0; fm < 4; fm++) {
        #pragma unroll
        for (int rr = 0; rr < 2; rr++) {
            int i = i0 + wm + fm*16 + g + rr*8;
            float rinv = 1.0f / g_rowsum[b*Ln + i];
            #pragma unroll
            for (int fn = 0; fn < 4; fn++) {
                int j = d0 + wn + fn*8 + th*2;
                float2 cv = *(const float2*)&Cb[(size_t)i*Dn + j];
                float2 pv = *(const float2*)&g_pe[i*Dn + j];
                float2 ov;
                ov.x = cv.x + pv.x + acc[fm][fn][rr*2+0]*rinv;
                ov.y = cv.y + pv.y + acc[fm][fn][rr*2+1]*rinv;
                *(float2*)&Tb[(size_t)i*Dn + j] = ov;
            }
        }
    }
}

// ---------------- 7) LN(tsum) + weighted mix ----------------------------------
__global__ __launch_bounds__(256)
void final_kernel(const float* __restrict__ wp,
                  const float* __restrict__ gt, const float* __restrict__ bt,
                  float* __restrict__ out) {
    __shared__ float red[8];
    int row = blockIdx.x;
    int t = row & (Ln - 1);
    int tid = threadIdx.x;
    int dA = tid, dB = tid + 256;
    const float* tp = g_tsum + (size_t)row*Dn;
    float v0 = tp[dA], v1 = tp[dB];
    float mu = blockReduce(v0 + v1, red) * (1.0f/Dn);
    float c0 = v0 - mu, c1 = v1 - mu;
    float var = blockReduce(c0*c0 + c1*c1, red) * (1.0f/Dn);
    float inv = rsqrtf(var + EPSf);
    float w0 = wp[0], w1 = wp[1], w2 = wp[2], w3 = wp[3];
    float mx = fmaxf(fmaxf(w0, w1), fmaxf(w2, w3));
    float e0 = expf(w0-mx), e1 = expf(w1-mx), e2 = expf(w2-mx), e3 = expf(w3-mx);
    float esum = 1.0f / (e0+e1+e2+e3);
    w0 = e0*esum; w1 = e1*esum; w2 = e2*esum; w3 = e3*esum;
    const float* cp = g_c + (size_t)row*Dn;
    float tpe0 = c0*inv*gt[dA] + bt[dA];
    float tpe1 = c1*inv*gt[dB] + bt[dB];
    out[(size_t)row*Dn + dA] = w0*cp[dA] + w1*g_pef[t*Dn+dA] + w2*g_pel[t*Dn+dA] + w3*tpe0;
    out[(size_t)row*Dn + dB] = w0*cp[dB] + w1*g_pef[t*Dn+dB] + w2*g_pel[t*Dn+dB] + w3*tpe1;
}

// ---------------- launch ------------------------------------------------------
extern "C" void kernel_launch(void* const* d_in, const int* in_sizes, int n_in,
                              void* d_out, int out_size) {
    const float* x          = (const float*)d_in[0];
    const float* conv_w     = (const float*)d_in[1];
    const float* conv_b     = (const float*)d_in[2];
    const float* pe_learned = (const float*)d_in[3];
    const float* wp         = (const float*)d_in[4];
    const float* gamma_c    = (const float*)d_in[5];
    const float* beta_c     = (const float*)d_in[6];
    const float* gamma_f    = (const float*)d_in[7];
    const float* beta_f     = (const float*)d_in[8];
    const float* gamma_l    = (const float*)d_in[9];
    const float* beta_l     = (const float*)d_in[10];
    const float* gamma_t    = (const float*)d_in[11];
    const float* beta_t     = (const float*)d_in[12];

    features_kernel<<<(Bn*Ln*Cn + 255)/256, 256>>>(x);
    conv_ln_kernel<<<dim3(Ln/TT, Bn), 256>>>(conv_w, conv_b, gamma_c, beta_c);
    pe_kernel<<<Ln, 256>>>(pe_learned, gamma_f, beta_f, gamma_l, beta_l);
    gram_kernel<<<dim3(136, Bn), 256>>>();
    rowsum_kernel<<<Bn*Ln/8, 256>>>();
    sem_kernel<<<dim3(16, 4, Bn), 256>>>();
    final_kernel<<<Bn*Ln, 256>>>(wp, gamma_t, beta_t, (float*)d_out);
}

// round 4
// speedup vs baseline: 2.5163x; 1.7975x over previous
#include <cuda_runtime.h>
#include <math.h>

#define Bn 8
#define Ln 2048
#define Cn 7
#define Dn 512
#define Wn 24
#define NF 56
#define EPSf 1e-5f
#define TT 16
#define THRESH 1e-12f

// ---------------- scratch (device globals; allocation-free kernel_launch) ----
__device__ float g_xcomb[Bn*Ln*NF];
__device__ float g_c[(size_t)Bn*Ln*Dn];
__device__ float g_sq[Bn*Ln];
__device__ float g_rowsum[Bn*Ln];
__device__ float g_pe[Ln*Dn];
__device__ float g_pef[Ln*Dn];
__device__ float g_pel[Ln*Dn];
__device__ float g_S[(size_t)Bn*Ln*Ln];
__device__ float g_tsum[(size_t)Bn*Ln*Dn];
__device__ int   g_flag[Bn*16*16];          // per-128x128-tile "S nonzero" flag

// ---------------- helpers -----------------------------------------------------
__device__ __forceinline__ float totf(float x) {
    unsigned u;
    asm("cvt.rna.tf32.f32 %0, %1;" : "=r"(u) : "f"(x));
    return __uint_as_float(u);
}

__device__ __forceinline__ void mma_tf32(float* d, const unsigned* a, const unsigned* b) {
    asm volatile(
        "mma.sync.aligned.m16n8k8.row.col.f32.tf32.tf32.f32 "
        "{%0,%1,%2,%3}, {%4,%5,%6,%7}, {%8,%9}, {%0,%1,%2,%3};"
        : "+f"(d[0]), "+f"(d[1]), "+f"(d[2]), "+f"(d[3])
        : "r"(a[0]), "r"(a[1]), "r"(a[2]), "r"(a[3]), "r"(b[0]), "r"(b[1]));
}

__device__ __forceinline__ float blockReduce(float v, float* red) {
    #pragma unroll
    for (int o = 16; o; o >>= 1) v += __shfl_xor_sync(0xffffffffu, v, o);
    if ((threadIdx.x & 31) == 0) red[threadIdx.x >> 5] = v;
    __syncthreads();
    float s = red[0];
    #pragma unroll
    for (int i = 1; i < 8; i++) s += red[i];
    __syncthreads();
    return s;
}

// ---------------- 1) window stats + lags --------------------------------------
__global__ __launch_bounds__(256)
void features_kernel(const float* __restrict__ x) {
    int gid = blockIdx.x * blockDim.x + threadIdx.x;
    if (gid >= Bn*Ln*Cn) return;
    int ch = gid % Cn;
    int t  = (gid / Cn) % Ln;
    int b  = gid / (Cn*Ln);
    const float* xb = x + (size_t)b*Ln*Cn;
    float v[Wn];
    #pragma unroll
    for (int w = 0; w < Wn; w++) {
        int tt = t - (Wn-1) + w; tt = tt < 0 ? 0 : tt;
        v[w] = xb[tt*Cn + ch];
    }
    float s = 0.f, mx = v[0], mn = v[0];
    #pragma unroll
    for (int w = 0; w < Wn; w++) { s += v[w]; mx = fmaxf(mx, v[w]); mn = fminf(mn, v[w]); }
    float mean = s * (1.0f/Wn);
    float m2 = 0.f;
    #pragma unroll
    for (int w = 0; w < Wn; w++) { float d = v[w]-mean; m2 += d*d; }
    float sd = sqrtf(m2 * (1.0f/(Wn-1)));
    float xc = v[Wn-1];
    int t3 = t-3; t3 = t3 < 0 ? 0 : t3;
    int t5 = t-5; t5 = t5 < 0 ? 0 : t5;
    int t7 = t-7; t7 = t7 < 0 ? 0 : t7;
    float* o = g_xcomb + ((size_t)b*Ln + t)*NF;
    o[ch]      = xc;
    o[7  + ch] = mean;
    o[14 + ch] = mx;
    o[21 + ch] = mn;
    o[28 + ch] = sd;
    o[35 + ch] = xc - xb[t3*Cn + ch];
    o[42 + ch] = xc - xb[t5*Cn + ch];
    o[49 + ch] = xc - xb[t7*Cn + ch];
}

// ---------------- 2) circular conv1d(k=3) + bias + LN + sumsq -----------------
__global__ __launch_bounds__(256)
void conv_ln_kernel(const float* __restrict__ conv_w, const float* __restrict__ conv_b,
                    const float* __restrict__ gamma_c, const float* __restrict__ beta_c) {
    __shared__ float sx[TT+2][NF];
    __shared__ float semb[TT][Dn];
    int b  = blockIdx.y;
    int t0 = blockIdx.x * TT;
    int tid = threadIdx.x;
    for (int i = tid; i < (TT+2)*NF; i += 256) {
        int r = i / NF, f = i - r*NF;
        int tt = (t0 - 1 + r + Ln) & (Ln - 1);
        sx[r][f] = g_xcomb[((size_t)b*Ln + tt)*NF + f];
    }
    __syncthreads();
    int d0 = tid * 2;
    float acc0[TT], acc1[TT];
    float bb0 = conv_b[d0], bb1 = conv_b[d0+1];
    #pragma unroll
    for (int t = 0; t < TT; t++) { acc0[t] = bb0; acc1[t] = bb1; }
    const float* w0p = conv_w + (size_t)d0*NF*3;
    const float* w1p = w0p + NF*3;
    for (int f = 0; f < NF; f++) {
        float w00 = w0p[f*3+0], w01 = w0p[f*3+1], w02 = w0p[f*3+2];
        float w10 = w1p[f*3+0], w11 = w1p[f*3+1], w12 = w1p[f*3+2];
        float sv[TT+2];
        #pragma unroll
        for (int r = 0; r < TT+2; r++) sv[r] = sx[r][f];
        #pragma unroll
        for (int t = 0; t < TT; t++) {
            acc0[t] += sv[t]*w00 + sv[t+1]*w01 + sv[t+2]*w02;
            acc1[t] += sv[t]*w10 + sv[t+1]*w11 + sv[t+2]*w12;
        }
    }
    #pragma unroll
    for (int t = 0; t < TT; t++) { semb[t][d0] = acc0[t]; semb[t][d0+1] = acc1[t]; }
    __syncthreads();
    int warp = tid >> 5, lane = tid & 31;
    for (int rr = warp; rr < TT; rr += 8) {
        float s = 0.f;
        for (int i = lane; i < Dn; i += 32) s += semb[rr][i];
        #pragma unroll
        for (int o = 16; o; o >>= 1) s += __shfl_xor_sync(0xffffffffu, s, o);
        float mu = s * (1.0f/Dn);
        float q = 0.f;
        for (int i = lane; i < Dn; i += 32) { float d = semb[rr][i]-mu; q += d*d; }
        #pragma unroll
        for (int o = 16; o; o >>= 1) q += __shfl_xor_sync(0xffffffffu, q, o);
        float inv = rsqrtf(q*(1.0f/Dn) + EPSf);
        int t = t0 + rr;
        float* cp = g_c + ((size_t)b*Ln + t)*Dn;
        float sq = 0.f;
        for (int i = lane; i < Dn; i += 32) {
            float cv = (semb[rr][i]-mu)*inv*gamma_c[i] + beta_c[i];
            cp[i] = cv;
            sq += cv*cv;
        }
        #pragma unroll
        for (int o = 16; o; o >>= 1) sq += __shfl_xor_sync(0xffffffffu, sq, o);
        if (lane == 0) g_sq[b*Ln + t] = sq;
    }
}

// ---------------- 3) sinusoid PE + LN(pe) + LN(pe_learned) --------------------
__global__ __launch_bounds__(256)
void pe_kernel(const float* __restrict__ pe_learned,
               const float* __restrict__ gf, const float* __restrict__ bf,
               const float* __restrict__ gl, const float* __restrict__ bl) {
    __shared__ float red[8];
    int t = blockIdx.x;
    int tid = threadIdx.x;
    int dA = tid, dB = tid + 256;
    const float kdiv = -9.210340371976184f / (float)Dn;
    float divA = expf((float)(dA & ~1) * kdiv);
    float divB = expf((float)(dB & ~1) * kdiv);
    float sA, cA, sB, cB;
    sincosf((float)t * divA, &sA, &cA);
    sincosf((float)t * divB, &sB, &cB);
    float v0 = (dA & 1) ? cA : sA;
    float v1 = (dB & 1) ? cB : sB;
    g_pe[t*Dn + dA] = v0;
    g_pe[t*Dn + dB] = v1;
    float mu = blockReduce(v0 + v1, red) * (1.0f/Dn);
    float c0 = v0 - mu, c1 = v1 - mu;
    float var = blockReduce(c0*c0 + c1*c1, red) * (1.0f/Dn);
    float inv = rsqrtf(var + EPSf);
    g_pef[t*Dn + dA] = c0*inv*gf[dA] + bf[dA];
    g_pef[t*Dn + dB] = c1*inv*gf[dB] + bf[dB];
    float u0 = pe_learned[t*Dn + dA], u1 = pe_learned[t*Dn + dB];
    float mu2 = blockReduce(u0 + u1, red) * (1.0f/Dn);
    float e0 = u0 - mu2, e1 = u1 - mu2;
    float var2 = blockReduce(e0*e0 + e1*e1, red) * (1.0f/Dn);
    float inv2 = rsqrtf(var2 + EPSf);
    g_pel[t*Dn + dA] = e0*inv2*gl[dA] + bl[dA];
    g_pel[t*Dn + dB] = e1*inv2*gl[dB] + bl[dB];
}

// ---------------- 4) symmetric Gram (tf32 mma) + exp + tile flags -------------
__global__ __launch_bounds__(256)
void gram_kernel() {
    __shared__ float As[2][128][20];
    __shared__ float Bs[2][128][20];
    __shared__ float redm[8];
    __shared__ int s_act;
    int b = blockIdx.y;
    int r = blockIdx.x, ti = 0;
    while (r >= 16 - ti) { r -= 16 - ti; ti++; }
    int tj = ti + r;
    const float* Cb = g_c + (size_t)b*Ln*Dn;
    int i0 = ti*128, j0 = tj*128;
    int tid = threadIdx.x;
    int warp = tid >> 5, lane = tid & 31;
    int wm = (warp >> 2) * 64;
    int wn = (warp & 3) * 32;
    int g = lane >> 2, th = lane & 3;

    int lrow = tid >> 1, lk = (tid & 1) * 8;
    const float* Ag = Cb + (size_t)(i0 + lrow)*Dn + lk;
    const float* Bg = Cb + (size_t)(j0 + lrow)*Dn + lk;

    float acc[4][4][4];
    #pragma unroll
    for (int i = 0; i < 4; i++)
        #pragma unroll
        for (int j = 0; j < 4; j++)
            #pragma unroll
            for (int q = 0; q < 4; q++) acc[i][j][q] = 0.f;

    float4 pa0 = *(const float4*)(Ag);
    float4 pa1 = *(const float4*)(Ag + 4);
    float4 pb0 = *(const float4*)(Bg);
    float4 pb1 = *(const float4*)(Bg + 4);
    #pragma unroll
    for (int q = 0; q < 4; q++) {
        As[0][lrow][lk+q]   = totf(((float*)&pa0)[q]);
        As[0][lrow][lk+4+q] = totf(((float*)&pa1)[q]);
        Bs[0][lrow][lk+q]   = totf(((float*)&pb0)[q]);
        Bs[0][lrow][lk+4+q] = totf(((float*)&pb1)[q]);
    }
    __syncthreads();
    int cur = 0;
    for (int kt = 0; kt < 32; kt++) {
        if (kt < 31) {
            int ko = (kt+1)*16;
            pa0 = *(const float4*)(Ag + ko);
            pa1 = *(const float4*)(Ag + ko + 4);
            pb0 = *(const float4*)(Bg + ko);
            pb1 = *(const float4*)(Bg + ko + 4);
        }
        #pragma unroll
        for (int k8 = 0; k8 < 16; k8 += 8) {
            unsigned af[4][4], bf_[4][2];
            #pragma unroll
            for (int fm = 0; fm < 4; fm++) {
                const float* ap = &As[cur][wm + fm*16 + g][k8 + th];
                af[fm][0] = __float_as_uint(ap[0]);
                af[fm][1] = __float_as_uint(ap[8*20]);
                af[fm][2] = __float_as_uint(ap[4]);
                af[fm][3] = __float_as_uint(ap[8*20 + 4]);
            }
            #pragma unroll
            for (int fn = 0; fn < 4; fn++) {
                const float* bp = &Bs[cur][wn + fn*8 + g][k8 + th];
                bf_[fn][0] = __float_as_uint(bp[0]);
                bf_[fn][1] = __float_as_uint(bp[4]);
            }
            #pragma unroll
            for (int fm = 0; fm < 4; fm++)
                #pragma unroll
                for (int fn = 0; fn < 4; fn++)
                    mma_tf32(acc[fm][fn], af[fm], bf_[fn]);
        }
        if (kt < 31) {
            int nxt = cur ^ 1;
            #pragma unroll
            for (int q = 0; q < 4; q++) {
                As[nxt][lrow][lk+q]   = totf(((float*)&pa0)[q]);
                As[nxt][lrow][lk+4+q] = totf(((float*)&pa1)[q]);
                Bs[nxt][lrow][lk+q]   = totf(((float*)&pb0)[q]);
                Bs[nxt][lrow][lk+4+q] = totf(((float*)&pb1)[q]);
            }
            __syncthreads();
            cur = nxt;
        }
    }
    // ---- epilogue: S = exp(-max(dist,0)/2) in-place in acc + tile max --------
    float sqj[4][2];
    #pragma unroll
    for (int fn = 0; fn < 4; fn++) {
        int j = j0 + wn + fn*8 + th*2;
        sqj[fn][0] = g_sq[b*Ln + j];
        sqj[fn][1] = g_sq[b*Ln + j + 1];
    }
    float mymax = 0.f;
    #pragma unroll
    for (int fm = 0; fm < 4; fm++) {
        #pragma unroll
        for (int rr = 0; rr < 2; rr++) {
            int i = i0 + wm + fm*16 + g + rr*8;
            float sqi = g_sq[b*Ln + i];
            #pragma unroll
            for (int fn = 0; fn < 4; fn++) {
                float d0v = fmaxf(sqi + sqj[fn][0] - 2.0f*acc[fm][fn][rr*2+0], 0.0f);
                float d1v = fmaxf(sqi + sqj[fn][1] - 2.0f*acc[fm][fn][rr*2+1], 0.0f);
                float s0 = __expf(-0.5f * d0v);
                float s1 = __expf(-0.5f * d1v);
                acc[fm][fn][rr*2+0] = s0;
                acc[fm][fn][rr*2+1] = s1;
                mymax = fmaxf(mymax, fmaxf(s0, s1));
            }
        }
    }
    #pragma unroll
    for (int o = 16; o; o >>= 1) mymax = fmaxf(mymax, __shfl_xor_sync(0xffffffffu, mymax, o));
    if (lane == 0) redm[warp] = mymax;
    __syncthreads();
    if (tid == 0) {
        float m = redm[0];
        #pragma unroll
        for (int i = 1; i < 8; i++) m = fmaxf(m, redm[i]);
        int a = (m > THRESH) ? 1 : 0;
        s_act = a;
        g_flag[b*256 + ti*16 + tj] = a;
        g_flag[b*256 + tj*16 + ti] = a;
    }
    __syncthreads();
    if (s_act) {
        float* Sb = g_S + (size_t)b*Ln*Ln;
        #pragma unroll
        for (int fm = 0; fm < 4; fm++) {
            #pragma unroll
            for (int rr = 0; rr < 2; rr++) {
                int i = i0 + wm + fm*16 + g + rr*8;
                #pragma unroll
                for (int fn = 0; fn < 4; fn++) {
                    int j = j0 + wn + fn*8 + th*2;
                    float s0 = acc[fm][fn][rr*2+0];
                    float s1 = acc[fm][fn][rr*2+1];
                    *(float2*)&Sb[(size_t)i*Ln + j] = make_float2(s0, s1);
                    if (ti != tj) {
                        Sb[(size_t)j*Ln + i]     = s0;
                        Sb[(size_t)(j+1)*Ln + i] = s1;
                    }
                }
            }
        }
    }
}

// ---------------- 5) row sums of S (active tiles only) ------------------------
__global__ __launch_bounds__(256)
void rowsum_kernel() {
    int row = blockIdx.x * 8 + (threadIdx.x >> 5);   // global row in [0, Bn*Ln)
    int lane = threadIdx.x & 31;
    int b  = row >> 11;
    int ti = (row & (Ln-1)) >> 7;
    const int* fl = g_flag + b*256 + ti*16;
    const float* Srow = g_S + (size_t)row * Ln;
    float s = 0.f;
    for (int tj = 0; tj < 16; tj++) {
        if (fl[tj]) {
            float4 v = *(const float4*)(Srow + tj*128 + lane*4);
            s += (v.x + v.y) + (v.z + v.w);
        }
    }
    #pragma unroll
    for (int o = 16; o; o >>= 1) s += __shfl_xor_sync(0xffffffffu, s, o);
    if (lane == 0) g_rowsum[row] = s;
}

// ---------------- 6) sem = S@c / rowsum over ACTIVE K chunks ------------------
__global__ __launch_bounds__(256)
void sem_kernel() {
    __shared__ float As[2][128][20];
    __shared__ float Bs[2][16][136];
    __shared__ int s_list[16];
    __shared__ int s_nact;
    int b  = blockIdx.z;
    int i0 = blockIdx.x * 128;
    int d0 = blockIdx.y * 128;
    const float* Cb = g_c + (size_t)b*Ln*Dn;
    const float* Sb = g_S + (size_t)b*Ln*Ln;
    int tid = threadIdx.x;
    int warp = tid >> 5, lane = tid & 31;
    int wm = (warp >> 2) * 64;
    int wn = (warp & 3) * 32;
    int g = lane >> 2, th = lane & 3;

    if (tid == 0) {
        const int* fl = g_flag + b*256 + (i0 >> 7)*16;
        int n = 0;
        #pragma unroll
        for (int tj = 0; tj < 16; tj++)
            if (fl[tj]) s_list[n++] = tj;
        s_nact = n;
    }
    __syncthreads();
    int total = s_nact * 8;      // BK=16 steps over active chunks

    int lrow = tid >> 1, lk = (tid & 1) * 8;
    int kB = tid >> 4, dB = (tid & 15) * 8;
    const float* Ag = Sb + (size_t)(i0 + lrow)*Ln + lk;
    const float* Bg = Cb + (size_t)kB*Dn + d0 + dB;

    float acc[4][4][4];
    #pragma unroll
    for (int i = 0; i < 4; i++)
        #pragma unroll
        for (int j = 0; j < 4; j++)
            #pragma unroll
            for (int q = 0; q < 4; q++) acc[i][j][q] = 0.f;

    int k0 = s_list[0] * 128;
    float4 pa0 = *(const float4*)(Ag + k0);
    float4 pa1 = *(const float4*)(Ag + k0 + 4);
    float4 pb0 = *(const float4*)(Bg + (size_t)k0*Dn);
    float4 pb1 = *(const float4*)(Bg + (size_t)k0*Dn + 4);
    #pragma unroll
    for (int q = 0; q < 4; q++) {
        As[0][lrow][lk+q]   = totf(((float*)&pa0)[q]);
        As[0][lrow][lk+4+q] = totf(((float*)&pa1)[q]);
        Bs[0][kB][dB+q]     = totf(((float*)&pb0)[q]);
        Bs[0][kB][dB+4+q]   = totf(((float*)&pb1)[q]);
    }
    __syncthreads();
    int cur = 0;
    for (int st = 0; st < total; st++) {
        if (st + 1 < total) {
            int kn = s_list[(st+1) >> 3] * 128 + ((st+1) & 7) * 16;
            pa0 = *(const float4*)(Ag + kn);
            pa1 = *(const float4*)(Ag + kn + 4);
            pb0 = *(const float4*)(Bg + (size_t)kn*Dn);
            pb1 = *(const float4*)(Bg + (size_t)kn*Dn + 4);
        }
        #pragma unroll
        for (int k8 = 0; k8 < 16; k8 += 8) {
            unsigned af[4][4], bf_[4][2];
            #pragma unroll
            for (int fm = 0; fm < 4; fm++) {
                const float* ap = &As[cur][wm + fm*16 + g][k8 + th];
                af[fm][0] = __float_as_uint(ap[0]);
                af[fm][1] = __float_as_uint(ap[8*20]);
                af[fm][2] = __float_as_uint(ap[4]);
                af[fm][3] = __float_as_uint(ap[8*20 + 4]);
            }
            #pragma unroll
            for (int fn = 0; fn < 4; fn++) {
                const float* bp = &Bs[cur][k8 + th][wn + fn*8 + g];
                bf_[fn][0] = __float_as_uint(bp[0]);
                bf_[fn][1] = __float_as_uint(bp[4*136]);
            }
            #pragma unroll
            for (int fm = 0; fm < 4; fm++)
                #pragma unroll
                for (int fn = 0; fn < 4; fn++)
                    mma_tf32(acc[fm][fn], af[fm], bf_[fn]);
        }
        if (st + 1 < total) {
            int nxt = cur ^ 1;
            #pragma unroll
            for (int q = 0; q < 4; q++) {
                As[nxt][lrow][lk+q]   = totf(((float*)&pa0)[q]);
                As[nxt][lrow][lk+4+q] = totf(((float*)&pa1)[q]);
                Bs[nxt][kB][dB+q]     = totf(((float*)&pb0)[q]);
                Bs[nxt][kB][dB+4+q]   = totf(((float*)&pb1)[q]);
            }
            __syncthreads();
            cur = nxt;
        }
    }
    float* Tb = g_tsum + (size_t)b*Ln*Dn;
    #pragma unroll
    for (int fm = 0; fm < 4; fm++) {
        #pragma unroll
        for (int rr = 0; rr < 2; rr++) {
            int i = i0 + wm + fm*16 + g + rr*8;
            float rinv = 1.0f / g_rowsum[b*Ln + i];
            #pragma unroll
            for (int fn = 0; fn < 4; fn++) {
                int j = d0 + wn + fn*8 + th*2;
                float2 cv = *(const float2*)&Cb[(size_t)i*Dn + j];
                float2 pv = *(const float2*)&g_pe[i*Dn + j];
                float2 ov;
                ov.x = cv.x + pv.x + acc[fm][fn][rr*2+0]*rinv;
                ov.y = cv.y + pv.y + acc[fm][fn][rr*2+1]*rinv;
                *(float2*)&Tb[(size_t)i*Dn + j] = ov;
            }
        }
    }
}

// ---------------- 7) LN(tsum) + weighted mix ----------------------------------
__global__ __launch_bounds__(256)
void final_kernel(const float* __restrict__ wp,
                  const float* __restrict__ gt, const float* __restrict__ bt,
                  float* __restrict__ out) {
    __shared__ float red[8];
    int row = blockIdx.x;
    int t = row & (Ln - 1);
    int tid = threadIdx.x;
    int dA = tid, dB = tid + 256;
    const float* tp = g_tsum + (size_t)row*Dn;
    float v0 = tp[dA], v1 = tp[dB];
    float mu = blockReduce(v0 + v1, red) * (1.0f/Dn);
    float c0 = v0 - mu, c1 = v1 - mu;
    float var = blockReduce(c0*c0 + c1*c1, red) * (1.0f/Dn);
    float inv = rsqrtf(var + EPSf);
    float w0 = wp[0], w1 = wp[1], w2 = wp[2], w3 = wp[3];
    float mx = fmaxf(fmaxf(w0, w1), fmaxf(w2, w3));
    float e0 = expf(w0-mx), e1 = expf(w1-mx), e2 = expf(w2-mx), e3 = expf(w3-mx);
    float esum = 1.0f / (e0+e1+e2+e3);
    w0 = e0*esum; w1 = e1*esum; w2 = e2*esum; w3 = e3*esum;
    const float* cp = g_c + (size_t)row*Dn;
    float tpe0 = c0*inv*gt[dA] + bt[dA];
    float tpe1 = c1*inv*gt[dB] + bt[dB];
    out[(size_t)row*Dn + dA] = w0*cp[dA] + w1*g_pef[t*Dn+dA] + w2*g_pel[t*Dn+dA] + w3*tpe0;
    out[(size_t)row*Dn + dB] = w0*cp[dB] + w1*g_pef[t*Dn+dB] + w2*g_pel[t*Dn+dB] + w3*tpe1;
}

// ---------------- launch ------------------------------------------------------
extern "C" void kernel_launch(void* const* d_in, const int* in_sizes, int n_in,
                              void* d_out, int out_size) {
    const float* x          = (const float*)d_in[0];
    const float* conv_w     = (const float*)d_in[1];
    const float* conv_b     = (const float*)d_in[2];
    const float* pe_learned = (const float*)d_in[3];
    const float* wp         = (const float*)d_in[4];
    const float* gamma_c    = (const float*)d_in[5];
    const float* beta_c     = (const float*)d_in[6];
    const float* gamma_f    = (const float*)d_in[7];
    const float* beta_f     = (const float*)d_in[8];
    const float* gamma_l    = (const float*)d_in[9];
    const float* beta_l     = (const float*)d_in[10];
    const float* gamma_t    = (const float*)d_in[11];
    const float* beta_t     = (const float*)d_in[12];

    features_kernel<<<(Bn*Ln*Cn + 255)/256, 256>>>(x);
    conv_ln_kernel<<<dim3(Ln/TT, Bn), 256>>>(conv_w, conv_b, gamma_c, beta_c);
    pe_kernel<<<Ln, 256>>>(pe_learned, gamma_f, beta_f, gamma_l, beta_l);
    gram_kernel<<<dim3(136, Bn), 256>>>();
    rowsum_kernel<<<Bn*Ln/8, 256>>>();
    sem_kernel<<<dim3(16, 4, Bn), 256>>>();
    final_kernel<<<Bn*Ln, 256>>>(wp, gamma_t, beta_t, (float*)d_out);
}